// round 1
// baseline (speedup 1.0000x reference)
#include <cuda_runtime.h>
#include <cstdint>

// ---------------------------------------------------------------------------
// EVEMixtralSparseBlock: T=8192 tokens, H=2048, F=4096, E=8 experts top-2 +
// shared expert. Output = [out (T*H f32), router_logits (T*E f32)].
//
// Round 0: TF32 tensor-core GEMMs (mma.sync.m16n8k8), dense-masked experts.
//   1) router_kernel: logits + top-2 softmax combine weights
//   2) per expert: gemm13 (fused silu(x w1^T) * (x w3^T) -> H1 scratch)
//                  gemm2  (out (+)= (H1 w2^T) * combine)
// ---------------------------------------------------------------------------

constexpr int TTOK = 8192;
constexpr int HDIM = 2048;
constexpr int FDIM = 4096;
constexpr int NEXP = 8;

constexpr int BM = 128, BN = 128, BK = 32;
constexpr int LDT   = BK + 4;        // 36 floats per smem row (conflict-free)
constexpr int TILEF = BM * LDT;      // floats per tile stage

// Scratch (device globals: no allocations allowed)
__device__ float g_combine[TTOK * NEXP];
__device__ float g_h1[(size_t)TTOK * FDIM];

// ---------------------------------------------------------------------------
// helpers
// ---------------------------------------------------------------------------
__device__ __forceinline__ uint32_t f2tf32(float f) {
    uint32_t u;
    asm("cvt.rna.tf32.f32 %0, %1;" : "=r"(u) : "f"(f));
    return u;
}

__device__ __forceinline__ void cp_async16(uint32_t dst, const void* src) {
    asm volatile("cp.async.cg.shared.global [%0], [%1], 16;\n" :: "r"(dst), "l"(src));
}
__device__ __forceinline__ void cp_commit() {
    asm volatile("cp.async.commit_group;\n");
}
template <int N>
__device__ __forceinline__ void cp_wait() {
    asm volatile("cp.async.wait_group %0;\n" :: "n"(N));
}

__device__ __forceinline__ void mma_tf32(float c[4], const uint32_t a[4], const uint32_t b[2]) {
    asm volatile(
        "mma.sync.aligned.m16n8k8.row.col.f32.tf32.tf32.f32 "
        "{%0,%1,%2,%3},{%4,%5,%6,%7},{%8,%9},{%0,%1,%2,%3};"
        : "+f"(c[0]), "+f"(c[1]), "+f"(c[2]), "+f"(c[3])
        : "r"(a[0]), "r"(a[1]), "r"(a[2]), "r"(a[3]), "r"(b[0]), "r"(b[1]));
}

// load a 128x32 fp32 tile (row-major source, ld elements/row) into smem stage
__device__ __forceinline__ void load_tile(float* sbuf, const float* __restrict__ src,
                                          int ld, int row0, int col0, int tid) {
    uint32_t sbase = (uint32_t)__cvta_generic_to_shared(sbuf);
    #pragma unroll
    for (int i = 0; i < 4; i++) {
        int c  = tid + i * 256;     // 0..1023 chunks of 16B
        int r  = c >> 3;
        int cc = c & 7;
        const float* s = src + (size_t)(row0 + r) * ld + col0 + cc * 4;
        cp_async16(sbase + (uint32_t)(r * LDT + cc * 4) * 4u, s);
    }
}

// ---------------------------------------------------------------------------
// router: logits [T,E] + top-2 combine weights
// ---------------------------------------------------------------------------
__global__ void router_kernel(const float* __restrict__ x,
                              const float* __restrict__ rw,
                              const float* __restrict__ rb,
                              float* __restrict__ logits_out) {
    __shared__ float sl[NEXP];
    const int t    = blockIdx.x;
    const int warp = threadIdx.x >> 5;
    const int lane = threadIdx.x & 31;
    const float* xt = x + (size_t)t * HDIM;
    const float* w  = rw + warp * HDIM;
    float s = 0.f;
    #pragma unroll 8
    for (int i = 0; i < HDIM / 32; i++)
        s = fmaf(xt[lane + 32 * i], w[lane + 32 * i], s);
    #pragma unroll
    for (int o = 16; o > 0; o >>= 1) s += __shfl_xor_sync(0xffffffffu, s, o);
    if (lane == 0) sl[warp] = s + rb[warp];
    __syncthreads();
    if (threadIdx.x == 0) {
        float l[NEXP];
        #pragma unroll
        for (int e = 0; e < NEXP; e++) l[e] = sl[e];
        int i1 = 0;
        #pragma unroll
        for (int e = 1; e < NEXP; e++) if (l[e] > l[i1]) i1 = e;
        int i2 = (i1 == 0) ? 1 : 0;
        #pragma unroll
        for (int e = 0; e < NEXP; e++) if (e != i1 && l[e] > l[i2]) i2 = e;
        // normalized top-2 weights == softmax over {l[i1], l[i2]}
        float e2 = expf(l[i2] - l[i1]);
        float w1 = 1.f / (1.f + e2);
        float w2 = e2 / (1.f + e2);
        #pragma unroll
        for (int e = 0; e < NEXP; e++) {
            logits_out[(size_t)t * NEXP + e] = l[e];
            g_combine[t * NEXP + e] = (e == i1) ? w1 : ((e == i2) ? w2 : 0.f);
        }
    }
}

// ---------------------------------------------------------------------------
// gemm13: H1[t,f] = silu(x·w1^T) * (x·w3^T), shared A tile, dual accumulators
// grid: (TTOK/128, FDIM/128); K = HDIM
// ---------------------------------------------------------------------------
__global__ void __launch_bounds__(256, 1)
gemm13_kernel(const float* __restrict__ X,
              const float* __restrict__ W1,
              const float* __restrict__ W3) {
    extern __shared__ float smem[];
    float* As  = smem;
    float* B1s = smem + 2 * TILEF;
    float* B3s = smem + 4 * TILEF;

    const int row0 = blockIdx.x * BM;
    const int n0   = blockIdx.y * BN;
    const int tid  = threadIdx.x;
    const int warp = tid >> 5, lane = tid & 31;
    const int wm = warp >> 1, wn = warp & 1;
    const int g = lane >> 2, tq = lane & 3;

    float acc1[2][8][4], acc3[2][8][4];
    #pragma unroll
    for (int a = 0; a < 2; a++)
        #pragma unroll
        for (int b = 0; b < 8; b++)
            #pragma unroll
            for (int c = 0; c < 4; c++) { acc1[a][b][c] = 0.f; acc3[a][b][c] = 0.f; }

    constexpr int KT = HDIM / BK;
    load_tile(As,  X,  HDIM, row0, 0, tid);
    load_tile(B1s, W1, HDIM, n0,   0, tid);
    load_tile(B3s, W3, HDIM, n0,   0, tid);
    cp_commit();

    for (int kt = 0; kt < KT; kt++) {
        if (kt + 1 < KT) {
            const int st = (kt + 1) & 1, k0 = (kt + 1) * BK;
            load_tile(As  + st * TILEF, X,  HDIM, row0, k0, tid);
            load_tile(B1s + st * TILEF, W1, HDIM, n0,   k0, tid);
            load_tile(B3s + st * TILEF, W3, HDIM, n0,   k0, tid);
            cp_commit();
            cp_wait<1>();
        } else {
            cp_wait<0>();
        }
        __syncthreads();
        const float* Ab  = As  + (kt & 1) * TILEF;
        const float* B1b = B1s + (kt & 1) * TILEF;
        const float* B3b = B3s + (kt & 1) * TILEF;
        #pragma unroll
        for (int kk = 0; kk < BK / 8; kk++) {
            const int k8 = kk * 8;
            uint32_t af[2][4];
            #pragma unroll
            for (int mt = 0; mt < 2; mt++) {
                const int rb = wm * 32 + mt * 16;
                af[mt][0] = f2tf32(Ab[(rb + g)     * LDT + k8 + tq]);
                af[mt][1] = f2tf32(Ab[(rb + g + 8) * LDT + k8 + tq]);
                af[mt][2] = f2tf32(Ab[(rb + g)     * LDT + k8 + tq + 4]);
                af[mt][3] = f2tf32(Ab[(rb + g + 8) * LDT + k8 + tq + 4]);
            }
            #pragma unroll
            for (int nt = 0; nt < 8; nt++) {
                const int cb = wn * 64 + nt * 8;
                uint32_t b1f[2], b3f[2];
                b1f[0] = f2tf32(B1b[(cb + g) * LDT + k8 + tq]);
                b1f[1] = f2tf32(B1b[(cb + g) * LDT + k8 + tq + 4]);
                b3f[0] = f2tf32(B3b[(cb + g) * LDT + k8 + tq]);
                b3f[1] = f2tf32(B3b[(cb + g) * LDT + k8 + tq + 4]);
                mma_tf32(acc1[0][nt], af[0], b1f);
                mma_tf32(acc1[1][nt], af[1], b1f);
                mma_tf32(acc3[0][nt], af[0], b3f);
                mma_tf32(acc3[1][nt], af[1], b3f);
            }
        }
        __syncthreads();
    }

    // epilogue: h1 = silu(c1) * c3
    #pragma unroll
    for (int mt = 0; mt < 2; mt++) {
        #pragma unroll
        for (int nt = 0; nt < 8; nt++) {
            #pragma unroll
            for (int j = 0; j < 4; j++) {
                const int r = row0 + wm * 32 + mt * 16 + g + ((j >= 2) ? 8 : 0);
                const int c = n0 + wn * 64 + nt * 8 + 2 * tq + (j & 1);
                const float a = acc1[mt][nt][j];
                const float h = a / (1.f + __expf(-a)) * acc3[mt][nt][j];
                g_h1[(size_t)r * FDIM + c] = h;
            }
        }
    }
}

// ---------------------------------------------------------------------------
// gemm2: OUT[t,h] (+)= (H1 · w2^T)[t,h] * combine[t,e]
// grid: (TTOK/128, HDIM/128); K = FDIM
// ---------------------------------------------------------------------------
__global__ void __launch_bounds__(256, 1)
gemm2_kernel(const float* __restrict__ W2,
             float* __restrict__ OUT,
             int use_cmb, int expert) {
    extern __shared__ float smem[];
    float* As = smem;
    float* Bs = smem + 2 * TILEF;

    const int row0 = blockIdx.x * BM;
    const int n0   = blockIdx.y * BN;
    const int tid  = threadIdx.x;
    const int warp = tid >> 5, lane = tid & 31;
    const int wm = warp >> 1, wn = warp & 1;
    const int g = lane >> 2, tq = lane & 3;

    float acc[2][8][4];
    #pragma unroll
    for (int a = 0; a < 2; a++)
        #pragma unroll
        for (int b = 0; b < 8; b++)
            #pragma unroll
            for (int c = 0; c < 4; c++) acc[a][b][c] = 0.f;

    const float* A = g_h1;
    constexpr int KT = FDIM / BK;
    load_tile(As, A,  FDIM, row0, 0, tid);
    load_tile(Bs, W2, FDIM, n0,   0, tid);
    cp_commit();

    for (int kt = 0; kt < KT; kt++) {
        if (kt + 1 < KT) {
            const int st = (kt + 1) & 1, k0 = (kt + 1) * BK;
            load_tile(As + st * TILEF, A,  FDIM, row0, k0, tid);
            load_tile(Bs + st * TILEF, W2, FDIM, n0,   k0, tid);
            cp_commit();
            cp_wait<1>();
        } else {
            cp_wait<0>();
        }
        __syncthreads();
        const float* Ab = As + (kt & 1) * TILEF;
        const float* Bb = Bs + (kt & 1) * TILEF;
        #pragma unroll
        for (int kk = 0; kk < BK / 8; kk++) {
            const int k8 = kk * 8;
            uint32_t af[2][4];
            #pragma unroll
            for (int mt = 0; mt < 2; mt++) {
                const int rb = wm * 32 + mt * 16;
                af[mt][0] = f2tf32(Ab[(rb + g)     * LDT + k8 + tq]);
                af[mt][1] = f2tf32(Ab[(rb + g + 8) * LDT + k8 + tq]);
                af[mt][2] = f2tf32(Ab[(rb + g)     * LDT + k8 + tq + 4]);
                af[mt][3] = f2tf32(Ab[(rb + g + 8) * LDT + k8 + tq + 4]);
            }
            #pragma unroll
            for (int nt = 0; nt < 8; nt++) {
                const int cb = wn * 64 + nt * 8;
                uint32_t bf[2];
                bf[0] = f2tf32(Bb[(cb + g) * LDT + k8 + tq]);
                bf[1] = f2tf32(Bb[(cb + g) * LDT + k8 + tq + 4]);
                mma_tf32(acc[0][nt], af[0], bf);
                mma_tf32(acc[1][nt], af[1], bf);
            }
        }
        __syncthreads();
    }

    #pragma unroll
    for (int mt = 0; mt < 2; mt++) {
        #pragma unroll
        for (int nt = 0; nt < 8; nt++) {
            #pragma unroll
            for (int j = 0; j < 4; j++) {
                const int r = row0 + wm * 32 + mt * 16 + g + ((j >= 2) ? 8 : 0);
                const int c = n0 + wn * 64 + nt * 8 + 2 * tq + (j & 1);
                const size_t idx = (size_t)r * HDIM + c;
                const float v = acc[mt][nt][j];
                if (use_cmb) {
                    OUT[idx] += v * g_combine[r * NEXP + expert];
                } else {
                    OUT[idx] = v;   // shared expert: first write, covers poison
                }
            }
        }
    }
}

// ---------------------------------------------------------------------------
extern "C" void kernel_launch(void* const* d_in, const int* in_sizes, int n_in,
                              void* d_out, int out_size) {
    const float* x   = (const float*)d_in[0];
    const float* rw  = (const float*)d_in[1];
    const float* rb  = (const float*)d_in[2];
    const float* w1  = (const float*)d_in[3];
    const float* w2  = (const float*)d_in[4];
    const float* w3  = (const float*)d_in[5];
    const float* sw1 = (const float*)d_in[6];
    const float* sw2 = (const float*)d_in[7];
    const float* sw3 = (const float*)d_in[8];

    float* out    = (float*)d_out;
    float* logits = out + (size_t)TTOK * HDIM;

    const int smem13 = 6 * TILEF * 4;
    const int smem2  = 4 * TILEF * 4;
    cudaFuncSetAttribute(gemm13_kernel, cudaFuncAttributeMaxDynamicSharedMemorySize, smem13);
    cudaFuncSetAttribute(gemm2_kernel,  cudaFuncAttributeMaxDynamicSharedMemorySize, smem2);

    // router: logits + combine weights
    router_kernel<<<TTOK, 256>>>(x, rw, rb, logits);

    dim3 g13(TTOK / BM, FDIM / BN);
    dim3 g2 (TTOK / BM, HDIM / BN);

    // shared expert first (initializes OUT)
    gemm13_kernel<<<g13, 256, smem13>>>(x, sw1, sw3);
    gemm2_kernel <<<g2,  256, smem2 >>>(sw2, out, 0, 0);

    // routed experts (dense-masked this round)
    for (int e = 0; e < NEXP; e++) {
        const float* w1e = w1 + (size_t)e * FDIM * HDIM;
        const float* w3e = w3 + (size_t)e * FDIM * HDIM;
        const float* w2e = w2 + (size_t)e * HDIM * FDIM;
        gemm13_kernel<<<g13, 256, smem13>>>(x, w1e, w3e);
        gemm2_kernel <<<g2,  256, smem2 >>>(w2e, out, 1, e);
    }
}

// round 2
// speedup vs baseline: 2.9932x; 2.9932x over previous
#include <cuda_runtime.h>
#include <cstdint>

// ---------------------------------------------------------------------------
// EVEMixtralSparseBlock: T=8192, H=2048, F=4096, E=8 top-2 + shared expert.
// Output = [out (T*H f32), router_logits (T*E f32)].
//
// Round 1: token gather/scatter. Router builds per-expert token lists; routed
// experts run only on their assigned tokens (2*T rows total vs 8*T dense).
//   1) zero_counts
//   2) router_kernel: logits, top-2 weights, per-expert token lists
//   3) dense shared-expert gemm13 + gemm2 (initializes OUT)
//   4) fused gemm13_sparse over (m_tiles, n_tiles, experts), gathered A rows
//   5) fused gemm2_sparse, scatter atomicAdd into OUT
// ---------------------------------------------------------------------------

constexpr int TTOK = 8192;
constexpr int HDIM = 2048;
constexpr int FDIM = 4096;
constexpr int NEXP = 8;

constexpr int BM = 128, BN = 128, BK = 32;
constexpr int LDT   = BK + 4;        // 36 floats per smem row (conflict-free)
constexpr int TILEF = BM * LDT;      // floats per tile stage

// Scratch (device globals: no allocations allowed)
__device__ float g_h1[(size_t)TTOK * FDIM];                   // shared-expert H1
__device__ float g_h1s[(size_t)NEXP * TTOK * FDIM];           // per-expert H1
__device__ int   g_expcnt[NEXP];
__device__ int   g_tok[NEXP * TTOK];
__device__ float g_wt[NEXP * TTOK];

// ---------------------------------------------------------------------------
// helpers
// ---------------------------------------------------------------------------
__device__ __forceinline__ uint32_t f2tf32(float f) {
    uint32_t u;
    asm("cvt.rna.tf32.f32 %0, %1;" : "=r"(u) : "f"(f));
    return u;
}

__device__ __forceinline__ void cp_async16(uint32_t dst, const void* src) {
    asm volatile("cp.async.cg.shared.global [%0], [%1], 16;\n" :: "r"(dst), "l"(src));
}
__device__ __forceinline__ void cp_commit() {
    asm volatile("cp.async.commit_group;\n");
}
template <int N>
__device__ __forceinline__ void cp_wait() {
    asm volatile("cp.async.wait_group %0;\n" :: "n"(N));
}

__device__ __forceinline__ void mma_tf32(float c[4], const uint32_t a[4], const uint32_t b[2]) {
    asm volatile(
        "mma.sync.aligned.m16n8k8.row.col.f32.tf32.tf32.f32 "
        "{%0,%1,%2,%3},{%4,%5,%6,%7},{%8,%9},{%0,%1,%2,%3};"
        : "+f"(c[0]), "+f"(c[1]), "+f"(c[2]), "+f"(c[3])
        : "r"(a[0]), "r"(a[1]), "r"(a[2]), "r"(a[3]), "r"(b[0]), "r"(b[1]));
}

// load a 128x32 fp32 tile (row-major source, ld elements/row) into smem stage
__device__ __forceinline__ void load_tile(float* sbuf, const float* __restrict__ src,
                                          int ld, int row0, int col0, int tid) {
    uint32_t sbase = (uint32_t)__cvta_generic_to_shared(sbuf);
    #pragma unroll
    for (int i = 0; i < 4; i++) {
        int c  = tid + i * 256;     // 0..1023 chunks of 16B
        int r  = c >> 3;
        int cc = c & 7;
        const float* s = src + (size_t)(row0 + r) * ld + col0 + cc * 4;
        cp_async16(sbase + (uint32_t)(r * LDT + cc * 4) * 4u, s);
    }
}

// gathered variant: row r comes from token stok[r] of x (ld = HDIM)
__device__ __forceinline__ void load_tile_gather(float* sbuf, const float* __restrict__ src,
                                                 const int* __restrict__ stok,
                                                 int col0, int tid) {
    uint32_t sbase = (uint32_t)__cvta_generic_to_shared(sbuf);
    #pragma unroll
    for (int i = 0; i < 4; i++) {
        int c  = tid + i * 256;
        int r  = c >> 3;
        int cc = c & 7;
        const float* s = src + (size_t)stok[r] * HDIM + col0 + cc * 4;
        cp_async16(sbase + (uint32_t)(r * LDT + cc * 4) * 4u, s);
    }
}

// ---------------------------------------------------------------------------
__global__ void zero_counts_kernel() {
    if (threadIdx.x < NEXP) g_expcnt[threadIdx.x] = 0;
}

// ---------------------------------------------------------------------------
// router: logits [T,E], top-2 weights, per-expert token lists
// ---------------------------------------------------------------------------
__global__ void router_kernel(const float* __restrict__ x,
                              const float* __restrict__ rw,
                              const float* __restrict__ rb,
                              float* __restrict__ logits_out) {
    __shared__ float sl[NEXP];
    const int t    = blockIdx.x;
    const int warp = threadIdx.x >> 5;
    const int lane = threadIdx.x & 31;
    const float* xt = x + (size_t)t * HDIM;
    const float* w  = rw + warp * HDIM;
    float s = 0.f;
    #pragma unroll 8
    for (int i = 0; i < HDIM / 32; i++)
        s = fmaf(xt[lane + 32 * i], w[lane + 32 * i], s);
    #pragma unroll
    for (int o = 16; o > 0; o >>= 1) s += __shfl_xor_sync(0xffffffffu, s, o);
    if (lane == 0) sl[warp] = s + rb[warp];
    __syncthreads();
    if (threadIdx.x == 0) {
        float l[NEXP];
        #pragma unroll
        for (int e = 0; e < NEXP; e++) l[e] = sl[e];
        int i1 = 0;
        #pragma unroll
        for (int e = 1; e < NEXP; e++) if (l[e] > l[i1]) i1 = e;
        int i2 = (i1 == 0) ? 1 : 0;
        #pragma unroll
        for (int e = 0; e < NEXP; e++) if (e != i1 && l[e] > l[i2]) i2 = e;
        // normalized top-2 weights == softmax over {l[i1], l[i2]}
        float e2 = expf(l[i2] - l[i1]);
        float wa = 1.f / (1.f + e2);
        float wb = e2 / (1.f + e2);
        #pragma unroll
        for (int e = 0; e < NEXP; e++)
            logits_out[(size_t)t * NEXP + e] = l[e];
        int p1 = atomicAdd(&g_expcnt[i1], 1);
        g_tok[i1 * TTOK + p1] = t;
        g_wt [i1 * TTOK + p1] = wa;
        int p2 = atomicAdd(&g_expcnt[i2], 1);
        g_tok[i2 * TTOK + p2] = t;
        g_wt [i2 * TTOK + p2] = wb;
    }
}

// ---------------------------------------------------------------------------
// dense gemm13 (shared expert): H1 = silu(x w1^T) * (x w3^T)
// ---------------------------------------------------------------------------
__global__ void __launch_bounds__(256, 1)
gemm13_kernel(const float* __restrict__ X,
              const float* __restrict__ W1,
              const float* __restrict__ W3) {
    extern __shared__ float smem[];
    float* As  = smem;
    float* B1s = smem + 2 * TILEF;
    float* B3s = smem + 4 * TILEF;

    const int row0 = blockIdx.x * BM;
    const int n0   = blockIdx.y * BN;
    const int tid  = threadIdx.x;
    const int warp = tid >> 5, lane = tid & 31;
    const int wm = warp >> 1, wn = warp & 1;
    const int g = lane >> 2, tq = lane & 3;

    float acc1[2][8][4], acc3[2][8][4];
    #pragma unroll
    for (int a = 0; a < 2; a++)
        #pragma unroll
        for (int b = 0; b < 8; b++)
            #pragma unroll
            for (int c = 0; c < 4; c++) { acc1[a][b][c] = 0.f; acc3[a][b][c] = 0.f; }

    constexpr int KT = HDIM / BK;
    load_tile(As,  X,  HDIM, row0, 0, tid);
    load_tile(B1s, W1, HDIM, n0,   0, tid);
    load_tile(B3s, W3, HDIM, n0,   0, tid);
    cp_commit();

    for (int kt = 0; kt < KT; kt++) {
        if (kt + 1 < KT) {
            const int st = (kt + 1) & 1, k0 = (kt + 1) * BK;
            load_tile(As  + st * TILEF, X,  HDIM, row0, k0, tid);
            load_tile(B1s + st * TILEF, W1, HDIM, n0,   k0, tid);
            load_tile(B3s + st * TILEF, W3, HDIM, n0,   k0, tid);
            cp_commit();
            cp_wait<1>();
        } else {
            cp_wait<0>();
        }
        __syncthreads();
        const float* Ab  = As  + (kt & 1) * TILEF;
        const float* B1b = B1s + (kt & 1) * TILEF;
        const float* B3b = B3s + (kt & 1) * TILEF;
        #pragma unroll
        for (int kk = 0; kk < BK / 8; kk++) {
            const int k8 = kk * 8;
            uint32_t af[2][4];
            #pragma unroll
            for (int mt = 0; mt < 2; mt++) {
                const int rb = wm * 32 + mt * 16;
                af[mt][0] = f2tf32(Ab[(rb + g)     * LDT + k8 + tq]);
                af[mt][1] = f2tf32(Ab[(rb + g + 8) * LDT + k8 + tq]);
                af[mt][2] = f2tf32(Ab[(rb + g)     * LDT + k8 + tq + 4]);
                af[mt][3] = f2tf32(Ab[(rb + g + 8) * LDT + k8 + tq + 4]);
            }
            #pragma unroll
            for (int nt = 0; nt < 8; nt++) {
                const int cb = wn * 64 + nt * 8;
                uint32_t b1f[2], b3f[2];
                b1f[0] = f2tf32(B1b[(cb + g) * LDT + k8 + tq]);
                b1f[1] = f2tf32(B1b[(cb + g) * LDT + k8 + tq + 4]);
                b3f[0] = f2tf32(B3b[(cb + g) * LDT + k8 + tq]);
                b3f[1] = f2tf32(B3b[(cb + g) * LDT + k8 + tq + 4]);
                mma_tf32(acc1[0][nt], af[0], b1f);
                mma_tf32(acc1[1][nt], af[1], b1f);
                mma_tf32(acc3[0][nt], af[0], b3f);
                mma_tf32(acc3[1][nt], af[1], b3f);
            }
        }
        __syncthreads();
    }

    #pragma unroll
    for (int mt = 0; mt < 2; mt++) {
        #pragma unroll
        for (int nt = 0; nt < 8; nt++) {
            #pragma unroll
            for (int j = 0; j < 4; j++) {
                const int r = row0 + wm * 32 + mt * 16 + g + ((j >= 2) ? 8 : 0);
                const int c = n0 + wn * 64 + nt * 8 + 2 * tq + (j & 1);
                const float a = acc1[mt][nt][j];
                const float h = a / (1.f + __expf(-a)) * acc3[mt][nt][j];
                g_h1[(size_t)r * FDIM + c] = h;
            }
        }
    }
}

// ---------------------------------------------------------------------------
// dense gemm2 (shared expert): OUT = H1 · w2^T   (plain store, inits OUT)
// ---------------------------------------------------------------------------
__global__ void __launch_bounds__(256, 1)
gemm2_kernel(const float* __restrict__ W2, float* __restrict__ OUT) {
    extern __shared__ float smem[];
    float* As = smem;
    float* Bs = smem + 2 * TILEF;

    const int row0 = blockIdx.x * BM;
    const int n0   = blockIdx.y * BN;
    const int tid  = threadIdx.x;
    const int warp = tid >> 5, lane = tid & 31;
    const int wm = warp >> 1, wn = warp & 1;
    const int g = lane >> 2, tq = lane & 3;

    float acc[2][8][4];
    #pragma unroll
    for (int a = 0; a < 2; a++)
        #pragma unroll
        for (int b = 0; b < 8; b++)
            #pragma unroll
            for (int c = 0; c < 4; c++) acc[a][b][c] = 0.f;

    constexpr int KT = FDIM / BK;
    load_tile(As, g_h1, FDIM, row0, 0, tid);
    load_tile(Bs, W2,   FDIM, n0,   0, tid);
    cp_commit();

    for (int kt = 0; kt < KT; kt++) {
        if (kt + 1 < KT) {
            const int st = (kt + 1) & 1, k0 = (kt + 1) * BK;
            load_tile(As + st * TILEF, g_h1, FDIM, row0, k0, tid);
            load_tile(Bs + st * TILEF, W2,   FDIM, n0,   k0, tid);
            cp_commit();
            cp_wait<1>();
        } else {
            cp_wait<0>();
        }
        __syncthreads();
        const float* Ab = As + (kt & 1) * TILEF;
        const float* Bb = Bs + (kt & 1) * TILEF;
        #pragma unroll
        for (int kk = 0; kk < BK / 8; kk++) {
            const int k8 = kk * 8;
            uint32_t af[2][4];
            #pragma unroll
            for (int mt = 0; mt < 2; mt++) {
                const int rb = wm * 32 + mt * 16;
                af[mt][0] = f2tf32(Ab[(rb + g)     * LDT + k8 + tq]);
                af[mt][1] = f2tf32(Ab[(rb + g + 8) * LDT + k8 + tq]);
                af[mt][2] = f2tf32(Ab[(rb + g)     * LDT + k8 + tq + 4]);
                af[mt][3] = f2tf32(Ab[(rb + g + 8) * LDT + k8 + tq + 4]);
            }
            #pragma unroll
            for (int nt = 0; nt < 8; nt++) {
                const int cb = wn * 64 + nt * 8;
                uint32_t bf[2];
                bf[0] = f2tf32(Bb[(cb + g) * LDT + k8 + tq]);
                bf[1] = f2tf32(Bb[(cb + g) * LDT + k8 + tq + 4]);
                mma_tf32(acc[0][nt], af[0], bf);
                mma_tf32(acc[1][nt], af[1], bf);
            }
        }
        __syncthreads();
    }

    #pragma unroll
    for (int mt = 0; mt < 2; mt++) {
        #pragma unroll
        for (int nt = 0; nt < 8; nt++) {
            #pragma unroll
            for (int j = 0; j < 4; j++) {
                const int r = row0 + wm * 32 + mt * 16 + g + ((j >= 2) ? 8 : 0);
                const int c = n0 + wn * 64 + nt * 8 + 2 * tq + (j & 1);
                OUT[(size_t)r * HDIM + c] = acc[mt][nt][j];
            }
        }
    }
}

// ---------------------------------------------------------------------------
// sparse gemm13: per-expert gathered rows; grid (T/BM, F/BN, E)
// ---------------------------------------------------------------------------
__global__ void __launch_bounds__(256, 1)
gemm13_sparse(const float* __restrict__ X,
              const float* __restrict__ W1b,
              const float* __restrict__ W3b) {
    const int e    = blockIdx.z;
    const int cnt  = g_expcnt[e];
    const int row0 = blockIdx.x * BM;
    if (row0 >= cnt) return;

    extern __shared__ float smem[];
    float* As  = smem;
    float* B1s = smem + 2 * TILEF;
    float* B3s = smem + 4 * TILEF;
    __shared__ int stok[BM];

    const float* W1 = W1b + (size_t)e * FDIM * HDIM;
    const float* W3 = W3b + (size_t)e * FDIM * HDIM;

    const int n0  = blockIdx.y * BN;
    const int tid = threadIdx.x;
    const int warp = tid >> 5, lane = tid & 31;
    const int wm = warp >> 1, wn = warp & 1;
    const int g = lane >> 2, tq = lane & 3;

    if (tid < BM) stok[tid] = g_tok[e * TTOK + min(row0 + tid, cnt - 1)];
    __syncthreads();

    float acc1[2][8][4], acc3[2][8][4];
    #pragma unroll
    for (int a = 0; a < 2; a++)
        #pragma unroll
        for (int b = 0; b < 8; b++)
            #pragma unroll
            for (int c = 0; c < 4; c++) { acc1[a][b][c] = 0.f; acc3[a][b][c] = 0.f; }

    constexpr int KT = HDIM / BK;
    load_tile_gather(As,  X, stok, 0, tid);
    load_tile(B1s, W1, HDIM, n0, 0, tid);
    load_tile(B3s, W3, HDIM, n0, 0, tid);
    cp_commit();

    for (int kt = 0; kt < KT; kt++) {
        if (kt + 1 < KT) {
            const int st = (kt + 1) & 1, k0 = (kt + 1) * BK;
            load_tile_gather(As + st * TILEF, X, stok, k0, tid);
            load_tile(B1s + st * TILEF, W1, HDIM, n0, k0, tid);
            load_tile(B3s + st * TILEF, W3, HDIM, n0, k0, tid);
            cp_commit();
            cp_wait<1>();
        } else {
            cp_wait<0>();
        }
        __syncthreads();
        const float* Ab  = As  + (kt & 1) * TILEF;
        const float* B1b = B1s + (kt & 1) * TILEF;
        const float* B3b = B3s + (kt & 1) * TILEF;
        #pragma unroll
        for (int kk = 0; kk < BK / 8; kk++) {
            const int k8 = kk * 8;
            uint32_t af[2][4];
            #pragma unroll
            for (int mt = 0; mt < 2; mt++) {
                const int rb = wm * 32 + mt * 16;
                af[mt][0] = f2tf32(Ab[(rb + g)     * LDT + k8 + tq]);
                af[mt][1] = f2tf32(Ab[(rb + g + 8) * LDT + k8 + tq]);
                af[mt][2] = f2tf32(Ab[(rb + g)     * LDT + k8 + tq + 4]);
                af[mt][3] = f2tf32(Ab[(rb + g + 8) * LDT + k8 + tq + 4]);
            }
            #pragma unroll
            for (int nt = 0; nt < 8; nt++) {
                const int cb = wn * 64 + nt * 8;
                uint32_t b1f[2], b3f[2];
                b1f[0] = f2tf32(B1b[(cb + g) * LDT + k8 + tq]);
                b1f[1] = f2tf32(B1b[(cb + g) * LDT + k8 + tq + 4]);
                b3f[0] = f2tf32(B3b[(cb + g) * LDT + k8 + tq]);
                b3f[1] = f2tf32(B3b[(cb + g) * LDT + k8 + tq + 4]);
                mma_tf32(acc1[0][nt], af[0], b1f);
                mma_tf32(acc1[1][nt], af[1], b1f);
                mma_tf32(acc3[0][nt], af[0], b3f);
                mma_tf32(acc3[1][nt], af[1], b3f);
            }
        }
        __syncthreads();
    }

    float* H1e = g_h1s + (size_t)e * TTOK * FDIM;
    #pragma unroll
    for (int mt = 0; mt < 2; mt++) {
        #pragma unroll
        for (int nt = 0; nt < 8; nt++) {
            #pragma unroll
            for (int j = 0; j < 4; j++) {
                const int r = row0 + wm * 32 + mt * 16 + g + ((j >= 2) ? 8 : 0);
                const int c = n0 + wn * 64 + nt * 8 + 2 * tq + (j & 1);
                const float a = acc1[mt][nt][j];
                const float h = a / (1.f + __expf(-a)) * acc3[mt][nt][j];
                H1e[(size_t)r * FDIM + c] = h;
            }
        }
    }
}

// ---------------------------------------------------------------------------
// sparse gemm2: OUT[tok[r]] += (H1e · w2^T)[r] * wt[r];  grid (T/BM, H/BN, E)
// ---------------------------------------------------------------------------
__global__ void __launch_bounds__(256, 1)
gemm2_sparse(const float* __restrict__ W2b, float* __restrict__ OUT) {
    const int e    = blockIdx.z;
    const int cnt  = g_expcnt[e];
    const int row0 = blockIdx.x * BM;
    if (row0 >= cnt) return;

    extern __shared__ float smem[];
    float* As = smem;
    float* Bs = smem + 2 * TILEF;
    __shared__ int   stok[BM];
    __shared__ float swt[BM];

    const float* W2  = W2b + (size_t)e * HDIM * FDIM;
    const float* H1e = g_h1s + (size_t)e * TTOK * FDIM;

    const int n0  = blockIdx.y * BN;
    const int tid = threadIdx.x;
    const int warp = tid >> 5, lane = tid & 31;
    const int wm = warp >> 1, wn = warp & 1;
    const int g = lane >> 2, tq = lane & 3;

    if (tid < BM) {
        int idx = min(row0 + tid, cnt - 1);
        stok[tid] = g_tok[e * TTOK + idx];
        swt [tid] = g_wt [e * TTOK + idx];
    }
    __syncthreads();

    float acc[2][8][4];
    #pragma unroll
    for (int a = 0; a < 2; a++)
        #pragma unroll
        for (int b = 0; b < 8; b++)
            #pragma unroll
            for (int c = 0; c < 4; c++) acc[a][b][c] = 0.f;

    constexpr int KT = FDIM / BK;
    load_tile(As, H1e, FDIM, row0, 0, tid);
    load_tile(Bs, W2,  FDIM, n0,   0, tid);
    cp_commit();

    for (int kt = 0; kt < KT; kt++) {
        if (kt + 1 < KT) {
            const int st = (kt + 1) & 1, k0 = (kt + 1) * BK;
            load_tile(As + st * TILEF, H1e, FDIM, row0, k0, tid);
            load_tile(Bs + st * TILEF, W2,  FDIM, n0,   k0, tid);
            cp_commit();
            cp_wait<1>();
        } else {
            cp_wait<0>();
        }
        __syncthreads();
        const float* Ab = As + (kt & 1) * TILEF;
        const float* Bb = Bs + (kt & 1) * TILEF;
        #pragma unroll
        for (int kk = 0; kk < BK / 8; kk++) {
            const int k8 = kk * 8;
            uint32_t af[2][4];
            #pragma unroll
            for (int mt = 0; mt < 2; mt++) {
                const int rb = wm * 32 + mt * 16;
                af[mt][0] = f2tf32(Ab[(rb + g)     * LDT + k8 + tq]);
                af[mt][1] = f2tf32(Ab[(rb + g + 8) * LDT + k8 + tq]);
                af[mt][2] = f2tf32(Ab[(rb + g)     * LDT + k8 + tq + 4]);
                af[mt][3] = f2tf32(Ab[(rb + g + 8) * LDT + k8 + tq + 4]);
            }
            #pragma unroll
            for (int nt = 0; nt < 8; nt++) {
                const int cb = wn * 64 + nt * 8;
                uint32_t bf[2];
                bf[0] = f2tf32(Bb[(cb + g) * LDT + k8 + tq]);
                bf[1] = f2tf32(Bb[(cb + g) * LDT + k8 + tq + 4]);
                mma_tf32(acc[0][nt], af[0], bf);
                mma_tf32(acc[1][nt], af[1], bf);
            }
        }
        __syncthreads();
    }

    #pragma unroll
    for (int mt = 0; mt < 2; mt++) {
        #pragma unroll
        for (int nt = 0; nt < 8; nt++) {
            #pragma unroll
            for (int j = 0; j < 4; j++) {
                const int lr = wm * 32 + mt * 16 + g + ((j >= 2) ? 8 : 0);
                if (row0 + lr < cnt) {
                    const int c = n0 + wn * 64 + nt * 8 + 2 * tq + (j & 1);
                    atomicAdd(&OUT[(size_t)stok[lr] * HDIM + c],
                              acc[mt][nt][j] * swt[lr]);
                }
            }
        }
    }
}

// ---------------------------------------------------------------------------
extern "C" void kernel_launch(void* const* d_in, const int* in_sizes, int n_in,
                              void* d_out, int out_size) {
    const float* x   = (const float*)d_in[0];
    const float* rw  = (const float*)d_in[1];
    const float* rb  = (const float*)d_in[2];
    const float* w1  = (const float*)d_in[3];
    const float* w2  = (const float*)d_in[4];
    const float* w3  = (const float*)d_in[5];
    const float* sw1 = (const float*)d_in[6];
    const float* sw2 = (const float*)d_in[7];
    const float* sw3 = (const float*)d_in[8];

    float* out    = (float*)d_out;
    float* logits = out + (size_t)TTOK * HDIM;

    const int smem13 = 6 * TILEF * 4;
    const int smem2  = 4 * TILEF * 4;
    cudaFuncSetAttribute(gemm13_kernel, cudaFuncAttributeMaxDynamicSharedMemorySize, smem13);
    cudaFuncSetAttribute(gemm2_kernel,  cudaFuncAttributeMaxDynamicSharedMemorySize, smem2);
    cudaFuncSetAttribute(gemm13_sparse, cudaFuncAttributeMaxDynamicSharedMemorySize, smem13);
    cudaFuncSetAttribute(gemm2_sparse,  cudaFuncAttributeMaxDynamicSharedMemorySize, smem2);

    zero_counts_kernel<<<1, 32>>>();
    router_kernel<<<TTOK, 256>>>(x, rw, rb, logits);

    // shared expert (dense) — initializes OUT
    dim3 g13(TTOK / BM, FDIM / BN);
    dim3 g2 (TTOK / BM, HDIM / BN);
    gemm13_kernel<<<g13, 256, smem13>>>(x, sw1, sw3);
    gemm2_kernel <<<g2,  256, smem2 >>>(sw2, out);

    // routed experts (gathered), fused across experts
    dim3 s13(TTOK / BM, FDIM / BN, NEXP);
    dim3 s2 (TTOK / BM, HDIM / BN, NEXP);
    gemm13_sparse<<<s13, 256, smem13>>>(x, w1, w3);
    gemm2_sparse <<<s2,  256, smem2 >>>(w2, out);
}